// round 7
// baseline (speedup 1.0000x reference)
#include <cuda_runtime.h>
#include <cuda_fp16.h>
#include <cstdint>

// Problem constants
#define Tt 3
#define Bb 4
#define Nn 1024
#define Cc 512
#define Hh 8
#define Mrows (Tt*Bb*Nn)        // 12288
#define BNC (Bb*Nn*Cc)          // 2097152
#define THRESH 0.5f
#define DECAY 0.25f
#define SCALE 0.125f
#define EPSb 1e-5f
#define WSCALE 1024.0f
#define WUNSCALE (1.0f/1024.0f)

#define GEMM_SMEM (3*32768)     // 3 stages x (16KB A + 16KB B)

// ---------------- scratch (static device globals; no allocation) -------------
__device__ float  g_S0[3 * Mrows * Cc];           // 75.5 MB fp32 GEMM outputs
__device__ __half g_Ac[3 * Mrows * 1024];         // 75.5 MB split-A / spike-A
__device__ __half g_Wc[4 * Cc * 1024];            // 4 MB split weights (x1024)
__device__ uint32_t g_qw[Tt*Bb*Nn*16];
__device__ uint32_t g_kw[Tt*Bb*Nn*16];
__device__ uint32_t g_vw[Tt*Bb*Nn*16];
__device__ float    g_G[Tt*Bb*Hh*64*64];
__device__ float    g_part[3*96*2*Cc];            // per-(z, m-tile) BN partials
__device__ float    g_mean[3*Cc];
__device__ float    g_rstd[3*Cc];

// ---------------- helpers ----------------------------------------------------
__device__ __forceinline__ uint32_t smem_u32(const void* p) {
    uint32_t a;
    asm("{ .reg .u64 t; cvta.to.shared.u64 t, %1; cvt.u32.u64 %0, t; }"
        : "=r"(a) : "l"(p));
    return a;
}
#define SW128(off) ((off) ^ (((off) >> 3) & 0x70))

__device__ __forceinline__ void cpa16(uint32_t s, const void* g) {
    asm volatile("cp.async.cg.shared.global [%0], [%1], 16;"
                 :: "r"(s), "l"(g));
}
#define CPA_COMMIT()  asm volatile("cp.async.commit_group;" ::: "memory")
#define CPA_WAIT(n)   asm volatile("cp.async.wait_group %0;" :: "n"(n) : "memory")

__device__ __forceinline__ void ldsm4(uint32_t& r0, uint32_t& r1,
                                      uint32_t& r2, uint32_t& r3, uint32_t a) {
    asm volatile("ldmatrix.sync.aligned.m8n8.x4.shared.b16 {%0,%1,%2,%3}, [%4];"
                 : "=r"(r0), "=r"(r1), "=r"(r2), "=r"(r3) : "r"(a));
}
__device__ __forceinline__ void mma16816(float* c, const uint32_t* a,
                                         uint32_t b0, uint32_t b1) {
    asm volatile(
        "mma.sync.aligned.m16n8k16.row.col.f32.f16.f16.f32 "
        "{%0,%1,%2,%3}, {%4,%5,%6,%7}, {%8,%9}, {%0,%1,%2,%3};"
        : "+f"(c[0]), "+f"(c[1]), "+f"(c[2]), "+f"(c[3])
        : "r"(a[0]), "r"(a[1]), "r"(a[2]), "r"(a[3]), "r"(b0), "r"(b1));
}

// ---------------- fp32 -> 2x fp16 split --------------------------------------
__device__ __forceinline__ void split2(float x, __half& h, __half& m) {
    h = __float2half(x);
    m = __float2half(x - __half2float(h));
}

// ---- merged A split: q,k,v -> g_Ac[z], layout [hi(512) | mid(512)] ----------
__global__ void __launch_bounds__(256) split_A3(
    const float* __restrict__ q, const float* __restrict__ k,
    const float* __restrict__ v, __half* __restrict__ out)
{
    int z = blockIdx.y;
    const float* in = (z == 0) ? q : (z == 1) ? k : v;
    uint32_t gid = blockIdx.x * 256 + threadIdx.x;  // over Mrows*128 quads
    size_t m = gid >> 7;
    int c4 = (gid & 127) << 2;
    float4 x = *(const float4*)(in + m * Cc + c4);
    __half h0,m0,h1,m1,h2,m2,h3,m3;
    split2(x.x, h0, m0); split2(x.y, h1, m1);
    split2(x.z, h2, m2); split2(x.w, h3, m3);
    __half2* o = (__half2*)(out + (size_t)z * Mrows * 1024 + m * 1024 + c4);
    o[0] = __halves2half2(h0, h1);
    o[1] = __halves2half2(h2, h3);
    o[256] = __halves2half2(m0, m1);     // +512 halves
    o[257] = __halves2half2(m2, m3);
}

// ---- merged W split: Wq,Wk,Wv,Wp -> g_Wc[y], scaled x1024 -------------------
__global__ void __launch_bounds__(256) split_W4(
    const float* __restrict__ w0, const float* __restrict__ w1,
    const float* __restrict__ w2, const float* __restrict__ w3,
    __half* __restrict__ out)
{
    int y = blockIdx.y;
    const float* W = (y == 0) ? w0 : (y == 1) ? w1 : (y == 2) ? w2 : w3;
    uint32_t gid = blockIdx.x * 256 + threadIdx.x;  // over 512*128 quads
    size_t n = gid >> 7;
    int c4 = (gid & 127) << 2;
    float4 x = *(const float4*)(W + n * Cc + c4);
    x.x *= WSCALE; x.y *= WSCALE; x.z *= WSCALE; x.w *= WSCALE;
    __half h0,m0,h1,m1,h2,m2,h3,m3;
    split2(x.x, h0, m0); split2(x.y, h1, m1);
    split2(x.z, h2, m2); split2(x.w, h3, m3);
    __half2* o = (__half2*)(out + (size_t)y * Cc * 1024 + n * 1024 + c4);
    o[0] = __halves2half2(h0, h1);
    o[1] = __halves2half2(h2, h3);
    o[256] = __halves2half2(m0, m1);
    o[257] = __halves2half2(m2, m3);
}

// ---------------- fp16 mma.sync GEMM + fused BN partial stats ----------------
// out[m,n] = (sum_k' A*W)*2^-10 + bias[n]. 3-product split via segment mapping.
// isBranch=1: A=[Ah|Am] ldA=1024, 24 iters, segs (Ah,Wh),(Ah,Wm),(Am,Wh)
// isBranch=0: A=spikes ldA=512, 16 iters, segs (A,Wh),(A,Wm)
__global__ void __launch_bounds__(256) gemm_mma(
    const __half* __restrict__ Abase, const __half* __restrict__ W,
    const float* __restrict__ b0p, const float* __restrict__ b1p,
    const float* __restrict__ b2p, float* __restrict__ outBase,
    int kIters, int ldA, int isBranch)
{
    extern __shared__ char smem[];
    const uint32_t sbase = smem_u32(smem);
    const int tid = threadIdx.x;
    const int lane = tid & 31;
    const int wid = tid >> 5;
    const int wm = wid & 1;
    const int wn = wid >> 1;
    const int m0 = blockIdx.y * 128;
    const int n0 = blockIdx.x * 128;
    const int z  = blockIdx.z;

    const __half* A = Abase + (size_t)z * Mrows * (size_t)ldA;
    const float* bias = (z == 0) ? b0p : (z == 1) ? b1p : b2p;
    float* out = outBase + (size_t)z * Mrows * Cc;

    float acc[4][4][4];
    #pragma unroll
    for (int i = 0; i < 4; i++)
        #pragma unroll
        for (int j = 0; j < 4; j++)
            #pragma unroll
            for (int r = 0; r < 4; r++) acc[i][j][r] = 0.f;

    const int lr = tid >> 3;
    const int lc = tid & 7;

    const int arow = wm * 64 + (lane & 15);
    const uint32_t amask = (uint32_t)((arow & 7) << 4);
    const uint32_t akb0 = (uint32_t)((lane >> 4) * 16);
    const int brow = wn * 32 + (lane & 7) + ((lane >> 4) & 1) * 8;
    const uint32_t bmask = (uint32_t)((brow & 7) << 4);
    const uint32_t bkb0 = (uint32_t)(((lane >> 3) & 1) * 16);

    auto doLoad = [&](int it, int stage) {
        int in = (it & 7) * 64;
        int seg = it >> 3;
        int aoff, woff;
        if (isBranch) {
            aoff = (seg == 2 ? 512 : 0) + in;
            woff = (seg == 1 ? 512 : 0) + in;
        } else {
            aoff = in;
            woff = seg * 512 + in;
        }
        const __half* Ag = A + (size_t)m0 * ldA + aoff;
        const __half* Wg = W + (size_t)n0 * 1024 + woff;
        uint32_t as = sbase + stage * 32768;
        uint32_t bs = as + 16384;
        #pragma unroll
        for (int u = 0; u < 4; u++) {
            int r = lr + u * 32;
            uint32_t d = (uint32_t)SW128(r * 128 + lc * 16);
            cpa16(as + d, Ag + (size_t)r * ldA + lc * 8);
            cpa16(bs + d, Wg + (size_t)r * 1024 + lc * 8);
        }
    };

    doLoad(0, 0); CPA_COMMIT();
    doLoad(1, 1); CPA_COMMIT();

    for (int it = 0; it < kIters; it++) {
        if (it + 1 < kIters) { CPA_WAIT(1); } else { CPA_WAIT(0); }
        __syncthreads();
        if (it + 2 < kIters) {
            doLoad(it + 2, (it + 2) % 3);
            CPA_COMMIT();
        }
        const uint32_t as = sbase + (it % 3) * 32768;
        const uint32_t bs = as + 16384;
        #pragma unroll
        for (int ks = 0; ks < 4; ks++) {
            uint32_t ar[4][4];
            #pragma unroll
            for (int mi = 0; mi < 4; mi++) {
                uint32_t addr = as + (uint32_t)(arow + mi * 16) * 128
                              + (((uint32_t)(ks * 32) + akb0) ^ amask);
                ldsm4(ar[mi][0], ar[mi][1], ar[mi][2], ar[mi][3], addr);
            }
            uint32_t br[2][4];
            #pragma unroll
            for (int nh = 0; nh < 2; nh++) {
                uint32_t addr = bs + (uint32_t)(brow + nh * 16) * 128
                              + (((uint32_t)(ks * 32) + bkb0) ^ bmask);
                ldsm4(br[nh][0], br[nh][1], br[nh][2], br[nh][3], addr);
            }
            #pragma unroll
            for (int mi = 0; mi < 4; mi++)
                #pragma unroll
                for (int ni = 0; ni < 4; ni++) {
                    int nh = ni >> 1, p = ni & 1;
                    mma16816(acc[mi][ni], ar[mi], br[nh][p*2], br[nh][p*2+1]);
                }
        }
    }

    // ---- epilogue: unscale + bias, store, fused column stats ----
    __syncthreads();                      // smem now reused for stats
    float* spart = (float*)smem;          // [2 (s/s2)][2 (wm)][128]

    float ls[8], ls2[8];
    #pragma unroll
    for (int j = 0; j < 8; j++) { ls[j] = 0.f; ls2[j] = 0.f; }

    #pragma unroll
    for (int mi = 0; mi < 4; mi++) {
        int r0 = m0 + wm * 64 + mi * 16 + (lane >> 2);
        #pragma unroll
        for (int ni = 0; ni < 4; ni++) {
            int n = n0 + wn * 32 + ni * 8 + (lane & 3) * 2;
            float bb0 = bias[n], bb1 = bias[n + 1];
            float a0 = acc[mi][ni][0] * WUNSCALE + bb0;
            float a1 = acc[mi][ni][1] * WUNSCALE + bb1;
            float a2 = acc[mi][ni][2] * WUNSCALE + bb0;
            float a3 = acc[mi][ni][3] * WUNSCALE + bb1;
            float2 v0 = { a0, a1 };
            float2 v1 = { a2, a3 };
            *(float2*)(out + (size_t)r0 * Cc + n) = v0;
            *(float2*)(out + (size_t)(r0 + 8) * Cc + n) = v1;
            ls [ni*2]   += a0 + a2;
            ls2[ni*2]   += a0*a0 + a2*a2;
            ls [ni*2+1] += a1 + a3;
            ls2[ni*2+1] += a1*a1 + a3*a3;
        }
    }
    #pragma unroll
    for (int o = 4; o < 32; o <<= 1) {
        #pragma unroll
        for (int j = 0; j < 8; j++) {
            ls[j]  += __shfl_xor_sync(0xffffffffu, ls[j],  o);
            ls2[j] += __shfl_xor_sync(0xffffffffu, ls2[j], o);
        }
    }
    if (lane < 4) {
        #pragma unroll
        for (int j = 0; j < 8; j++) {
            int col = wn * 32 + (j >> 1) * 8 + lane * 2 + (j & 1);
            spart[wm * 128 + col]       = ls[j];
            spart[256 + wm * 128 + col] = ls2[j];
        }
    }
    __syncthreads();
    if (tid < 128) {
        float s  = spart[tid] + spart[128 + tid];
        float s2 = spart[256 + tid] + spart[384 + tid];
        int n = n0 + tid;
        g_part[((size_t)(z * 96 + blockIdx.y) * 2 + 0) * Cc + n] = s;
        g_part[((size_t)(z * 96 + blockIdx.y) * 2 + 1) * Cc + n] = s2;
    }
}

// ---------------- BN final stats (parallel: grid (nz,4), block 512) ----------
// Each block: 128 channels, 4 row-groups of 24 tiles each, fixed-order combine.
__global__ void __launch_bounds__(512) bn_stats_final()
{
    __shared__ float sp[8][128];
    int z  = blockIdx.x;
    int cb = blockIdx.y;                   // 0..3 -> channels cb*128..+127
    int cl = threadIdx.x & 127;
    int rg = threadIdx.x >> 7;             // 0..3
    int c  = cb * 128 + cl;
    float s = 0.f, s2 = 0.f;
    for (int i = 0; i < 24; i++) {
        int by = rg * 24 + i;
        s  += g_part[((size_t)(z * 96 + by) * 2 + 0) * Cc + c];
        s2 += g_part[((size_t)(z * 96 + by) * 2 + 1) * Cc + c];
    }
    sp[rg][cl] = s;
    sp[4 + rg][cl] = s2;
    __syncthreads();
    if (threadIdx.x < 128) {
        float ts  = (sp[0][cl] + sp[1][cl]) + (sp[2][cl] + sp[3][cl]);
        float ts2 = (sp[4][cl] + sp[5][cl]) + (sp[6][cl] + sp[7][cl]);
        float mean = ts / (float)Mrows;
        float var  = ts2 / (float)Mrows - mean * mean;
        g_mean[z * Cc + c] = mean;
        g_rstd[z * Cc + c] = rsqrtf(var + EPSb);
    }
}

// ------- merged BN apply + LIF + ballot bit-pack (q/k/v) ---------------------
__global__ void __launch_bounds__(512) bn_lif_bits(
    const float* __restrict__ Ybase,
    const float* __restrict__ g0, const float* __restrict__ g1,
    const float* __restrict__ g2,
    const float* __restrict__ e0, const float* __restrict__ e1,
    const float* __restrict__ e2,
    uint32_t* __restrict__ w0, uint32_t* __restrict__ w1,
    uint32_t* __restrict__ w2)
{
    int z = blockIdx.y;
    const float* Y = Ybase + (size_t)z * Mrows * Cc;
    const float* gamma = (z == 0) ? g0 : (z == 1) ? g1 : g2;
    const float* beta  = (z == 0) ? e0 : (z == 1) ? e1 : e2;
    uint32_t* bits     = (z == 0) ? w0 : (z == 1) ? w1 : w2;

    int bn = blockIdx.x;
    int c  = threadIdx.x;
    float mean = g_mean[z * Cc + c], rstd = g_rstd[z * Cc + c];
    float ga = gamma[c], be = beta[c];
    float mem = 0.f, spike = 0.f;
    #pragma unroll
    for (int t = 0; t < Tt; t++) {
        float y = Y[((size_t)t*4096 + bn)*Cc + c];
        float v = ga * (y - mean) * rstd + be;
        mem = (t == 0) ? v : (mem * DECAY * (1.f - spike) + v);
        bool fire = mem > THRESH;
        spike = fire ? 1.f : 0.f;
        unsigned mask = __ballot_sync(0xffffffffu, fire);
        if ((c & 31) == 0)
            bits[((size_t)t*4096 + bn)*16 + (c >> 5)] = mask;
    }
}

// ------- final stage: BN apply + LIF, write float spikes ---------------------
__global__ void __launch_bounds__(512) bn_lif_out(
    const float* __restrict__ Y, const float* __restrict__ gamma,
    const float* __restrict__ beta, float* __restrict__ out)
{
    int bn = blockIdx.x;
    int c  = threadIdx.x;
    float mean = g_mean[c], rstd = g_rstd[c];
    float ga = gamma[c], be = beta[c];
    float mem = 0.f, spike = 0.f;
    #pragma unroll
    for (int t = 0; t < Tt; t++) {
        float y = Y[((size_t)t*4096 + bn)*Cc + c];
        float v = ga * (y - mean) * rstd + be;
        mem = (t == 0) ? v : (mem * DECAY * (1.f - spike) + v);
        spike = (mem > THRESH) ? 1.f : 0.f;
        out[((size_t)t*4096 + bn)*Cc + c] = spike;
    }
}

// ---------------- G[j,d] = sum_m k[m,j]*v[m,d]  (per t,b,h) ------------------
__global__ void __launch_bounds__(256) build_G()
{
    int tbh = blockIdx.x;
    int h = tbh & 7;
    int tb = tbh >> 3;
    int tid = threadIdx.x;
    int lane = tid & 31;

    __shared__ uint32_t kc[64][32];
    __shared__ uint32_t vc[64][32];

    for (int m0 = tid; m0 < Nn; m0 += 256) {
        size_t row = (size_t)tb * Nn + m0;
        uint32_t k0 = g_kw[row*16 + 2*h],  k1 = g_kw[row*16 + 2*h + 1];
        uint32_t v0 = g_vw[row*16 + 2*h],  v1 = g_vw[row*16 + 2*h + 1];
        int w = m0 >> 5;
        #pragma unroll
        for (int j = 0; j < 32; j++) {
            unsigned mk = __ballot_sync(0xffffffffu, (k0 >> j) & 1u);
            if (lane == 0) kc[j][w] = mk;
            unsigned mk2 = __ballot_sync(0xffffffffu, (k1 >> j) & 1u);
            if (lane == 0) kc[j + 32][w] = mk2;
            unsigned mv = __ballot_sync(0xffffffffu, (v0 >> j) & 1u);
            if (lane == 0) vc[j][w] = mv;
            unsigned mv2 = __ballot_sync(0xffffffffu, (v1 >> j) & 1u);
            if (lane == 0) vc[j + 32][w] = mv2;
        }
    }
    __syncthreads();

    for (int e = tid; e < 4096; e += 256) {
        int j = e >> 6, d = e & 63;
        int s = 0;
        #pragma unroll
        for (int w = 0; w < 32; w++)
            s += __popc(kc[j][w] & vc[d][w]);
        g_G[(size_t)tbh*4096 + e] = (float)s;
    }
}

// ------- fused: X = SCALE * Q G  ->  LIF over t  ->  fp16 spikes to Ac -------
// grid (16, 32): x = n-block (64 rows), y = b*8+h. block 256: d=tid&63, grp=tid>>6.
__global__ void __launch_bounds__(256) attn_lif(__half* __restrict__ Aout)
{
    int bh = blockIdx.y;
    int b = bh >> 3;
    int h = bh & 7;
    int d   = threadIdx.x & 63;
    int grp = threadIdx.x >> 6;
    int nbase = blockIdx.x * 64 + grp * 16;

    float mem[16];
    uint32_t spk = 0;    // bit ns = spike state

    #pragma unroll
    for (int t = 0; t < Tt; t++) {
        int tbh = (t * Bb + b) * Hh + h;
        float Greg[64];
        #pragma unroll
        for (int j = 0; j < 64; j++)
            Greg[j] = g_G[(size_t)tbh * 4096 + j * 64 + d];

        size_t rowbase = (size_t)(t * Bb + b) * Nn + nbase;
        #pragma unroll
        for (int ns = 0; ns < 16; ns++) {
            size_t row = rowbase + ns;
            uint32_t q0 = g_qw[row * 16 + 2 * h];
            uint32_t q1 = g_qw[row * 16 + 2 * h + 1];
            unsigned long long qb = (unsigned long long)q0 |
                                    ((unsigned long long)q1 << 32);
            float acc = 0.f;
            #pragma unroll
            for (int j = 0; j < 64; j++)
                if ((qb >> j) & 1ULL) acc += Greg[j];
            float x = SCALE * acc;
            float sp = (spk >> ns) & 1u ? 1.f : 0.f;
            float m = (t == 0) ? x : (mem[ns] * DECAY * (1.f - sp) + x);
            mem[ns] = m;
            bool fire = m > THRESH;
            spk = fire ? (spk | (1u << ns)) : (spk & ~(1u << ns));
            // write fp16 spike: Ac[((t*4+b)*1024+n)*512 + h*64 + d]
            Aout[(((size_t)t * 4096) + (size_t)b * 1024 + nbase + ns) * 512
                 + h * 64 + d] = __float2half(fire ? 1.f : 0.f);
        }
    }
}

// ---------------- host launcher ----------------------------------------------
extern "C" void kernel_launch(void* const* d_in, const int* in_sizes, int n_in,
                              void* d_out, int out_size)
{
    (void)in_sizes; (void)n_in; (void)out_size;
    const float* q  = (const float*)d_in[0];
    const float* k  = (const float*)d_in[1];
    const float* v  = (const float*)d_in[2];
    const float* Wq = (const float*)d_in[3];
    const float* bq = (const float*)d_in[4];
    const float* gq = (const float*)d_in[5];
    const float* betaq = (const float*)d_in[6];
    const float* Wk = (const float*)d_in[7];
    const float* bk = (const float*)d_in[8];
    const float* gk = (const float*)d_in[9];
    const float* betak = (const float*)d_in[10];
    const float* Wv = (const float*)d_in[11];
    const float* bv = (const float*)d_in[12];
    const float* gv = (const float*)d_in[13];
    const float* betav = (const float*)d_in[14];
    const float* Wp = (const float*)d_in[15];
    const float* bp = (const float*)d_in[16];
    const float* gp = (const float*)d_in[17];
    const float* betap = (const float*)d_in[18];
    float* out = (float*)d_out;

    float *S0;
    __half *Ac, *Wc;
    uint32_t *qw, *kw, *vw;
    cudaGetSymbolAddress((void**)&S0, g_S0);
    cudaGetSymbolAddress((void**)&Ac, g_Ac);
    cudaGetSymbolAddress((void**)&Wc, g_Wc);
    cudaGetSymbolAddress((void**)&qw, g_qw);
    cudaGetSymbolAddress((void**)&kw, g_kw);
    cudaGetSymbolAddress((void**)&vw, g_vw);

    cudaFuncSetAttribute(gemm_mma,
                         cudaFuncAttributeMaxDynamicSharedMemorySize, GEMM_SMEM);

    // splits
    split_W4<<<dim3(256, 4), 256>>>(Wq, Wk, Wv, Wp, Wc);
    split_A3<<<dim3(6144, 3), 256>>>(q, k, v, Ac);

    // --- all 3 branch GEMMs in one launch (fused BN partial stats) ---
    gemm_mma<<<dim3(4, 96, 3), 256, GEMM_SMEM>>>(
        Ac, Wc, bq, bk, bv, S0, 24, 1024, 1);
    bn_stats_final<<<dim3(3, 4), 512>>>();
    bn_lif_bits<<<dim3(4096, 3), 512>>>(S0, gq, gk, gv, betaq, betak, betav,
                                        qw, kw, vw);

    // --- attention (collapsed: X = Q (K^T V) * SCALE) + LIF -> fp16 spikes ---
    build_G<<<Tt*Bb*Hh, 256>>>();
    attn_lif<<<dim3(16, 32), 256>>>(Ac);

    // --- projection + BN + LIF -> output ---
    gemm_mma<<<dim3(4, 96, 1), 256, GEMM_SMEM>>>(
        Ac, Wc + (size_t)3 * Cc * 1024, bp, bp, bp, S0, 16, 512, 0);
    bn_stats_final<<<dim3(1, 4), 512>>>();
    bn_lif_out<<<4096, 512>>>(S0, gp, betap, out);
}

// round 10
// speedup vs baseline: 1.0437x; 1.0437x over previous
#include <cuda_runtime.h>
#include <cuda_fp16.h>
#include <cstdint>

// Problem constants
#define Tt 3
#define Bb 4
#define Nn 1024
#define Cc 512
#define Hh 8
#define Mrows (Tt*Bb*Nn)        // 12288
#define BNC (Bb*Nn*Cc)          // 2097152
#define THRESH 0.5f
#define DECAY 0.25f
#define SCALE 0.125f
#define EPSb 1e-5f
#define WSCALE 1024.0f
#define WUNSCALE (1.0f/1024.0f)

#define GEMM_SMEM (3*32768)     // 3 stages x (16KB A + 16KB B)

// ---------------- scratch (static device globals; no allocation) -------------
__device__ float  g_S0[3 * Mrows * Cc];           // 75.5 MB fp32 GEMM outputs
__device__ __half g_Ac[3 * Mrows * 1024];         // 75.5 MB split-A / spike-A
__device__ __half g_Wc[4 * Cc * 1024];            // 4 MB split weights (x1024)
__device__ uint32_t g_qw[Tt*Bb*Nn*16];
__device__ uint32_t g_kw[Tt*Bb*Nn*16];
__device__ uint32_t g_vw[Tt*Bb*Nn*16];
__device__ float    g_G[Tt*Bb*Hh*64*64];
__device__ float    g_part[3*96*2*Cc];            // per-(z, m-tile) BN partials
__device__ float    g_mean[3*Cc];
__device__ float    g_rstd[3*Cc];

// ---------------- helpers ----------------------------------------------------
__device__ __forceinline__ uint32_t smem_u32(const void* p) {
    uint32_t a;
    asm("{ .reg .u64 t; cvta.to.shared.u64 t, %1; cvt.u32.u64 %0, t; }"
        : "=r"(a) : "l"(p));
    return a;
}
#define SW128(off) ((off) ^ (((off) >> 3) & 0x70))

__device__ __forceinline__ void cpa16(uint32_t s, const void* g) {
    asm volatile("cp.async.cg.shared.global [%0], [%1], 16;"
                 :: "r"(s), "l"(g));
}
#define CPA_COMMIT()  asm volatile("cp.async.commit_group;" ::: "memory")
#define CPA_WAIT(n)   asm volatile("cp.async.wait_group %0;" :: "n"(n) : "memory")

__device__ __forceinline__ void ldsm4(uint32_t& r0, uint32_t& r1,
                                      uint32_t& r2, uint32_t& r3, uint32_t a) {
    asm volatile("ldmatrix.sync.aligned.m8n8.x4.shared.b16 {%0,%1,%2,%3}, [%4];"
                 : "=r"(r0), "=r"(r1), "=r"(r2), "=r"(r3) : "r"(a));
}
__device__ __forceinline__ void mma16816(float* c, const uint32_t* a,
                                         uint32_t b0, uint32_t b1) {
    asm volatile(
        "mma.sync.aligned.m16n8k16.row.col.f32.f16.f16.f32 "
        "{%0,%1,%2,%3}, {%4,%5,%6,%7}, {%8,%9}, {%0,%1,%2,%3};"
        : "+f"(c[0]), "+f"(c[1]), "+f"(c[2]), "+f"(c[3])
        : "r"(a[0]), "r"(a[1]), "r"(a[2]), "r"(a[3]), "r"(b0), "r"(b1));
}

// ---------------- fp32 -> 2x fp16 split --------------------------------------
__device__ __forceinline__ void split2(float x, __half& h, __half& m) {
    h = __float2half(x);
    m = __float2half(x - __half2float(h));
}

// ---- merged A split: q,k,v -> g_Ac[z], layout [hi(512) | mid(512)] ----------
__global__ void __launch_bounds__(256) split_A3(
    const float* __restrict__ q, const float* __restrict__ k,
    const float* __restrict__ v, __half* __restrict__ out)
{
    int z = blockIdx.y;
    const float* in = (z == 0) ? q : (z == 1) ? k : v;
    uint32_t gid = blockIdx.x * 256 + threadIdx.x;  // over Mrows*128 quads
    size_t m = gid >> 7;
    int c4 = (gid & 127) << 2;
    float4 x = *(const float4*)(in + m * Cc + c4);
    __half h0,m0,h1,m1,h2,m2,h3,m3;
    split2(x.x, h0, m0); split2(x.y, h1, m1);
    split2(x.z, h2, m2); split2(x.w, h3, m3);
    __half2* o = (__half2*)(out + (size_t)z * Mrows * 1024 + m * 1024 + c4);
    o[0] = __halves2half2(h0, h1);
    o[1] = __halves2half2(h2, h3);
    o[256] = __halves2half2(m0, m1);     // +512 halves
    o[257] = __halves2half2(m2, m3);
}

// ---- merged W split: Wq,Wk,Wv,Wp -> g_Wc[y], scaled x1024 -------------------
__global__ void __launch_bounds__(256) split_W4(
    const float* __restrict__ w0, const float* __restrict__ w1,
    const float* __restrict__ w2, const float* __restrict__ w3,
    __half* __restrict__ out)
{
    int y = blockIdx.y;
    const float* W = (y == 0) ? w0 : (y == 1) ? w1 : (y == 2) ? w2 : w3;
    uint32_t gid = blockIdx.x * 256 + threadIdx.x;  // over 512*128 quads
    size_t n = gid >> 7;
    int c4 = (gid & 127) << 2;
    float4 x = *(const float4*)(W + n * Cc + c4);
    x.x *= WSCALE; x.y *= WSCALE; x.z *= WSCALE; x.w *= WSCALE;
    __half h0,m0,h1,m1,h2,m2,h3,m3;
    split2(x.x, h0, m0); split2(x.y, h1, m1);
    split2(x.z, h2, m2); split2(x.w, h3, m3);
    __half2* o = (__half2*)(out + (size_t)y * Cc * 1024 + n * 1024 + c4);
    o[0] = __halves2half2(h0, h1);
    o[1] = __halves2half2(h2, h3);
    o[256] = __halves2half2(m0, m1);
    o[257] = __halves2half2(m2, m3);
}

// ---------------- fp16 mma.sync GEMM + fused BN partial stats ----------------
// out[m,n] = (sum_k' A*W)*2^-10 + bias[n]. 3-product split via segment mapping.
// isBranch=1: A=[Ah|Am] ldA=1024, 24 iters, segs (Ah,Wh),(Ah,Wm),(Am,Wh)
// isBranch=0: A=spikes ldA=512, 16 iters, segs (A,Wh),(A,Wm)
__global__ void __launch_bounds__(256) gemm_mma(
    const __half* __restrict__ Abase, const __half* __restrict__ W,
    const float* __restrict__ b0p, const float* __restrict__ b1p,
    const float* __restrict__ b2p, float* __restrict__ outBase,
    int kIters, int ldA, int isBranch)
{
    extern __shared__ char smem[];
    const uint32_t sbase = smem_u32(smem);
    const int tid = threadIdx.x;
    const int lane = tid & 31;
    const int wid = tid >> 5;
    const int wm = wid & 1;
    const int wn = wid >> 1;
    const int m0 = blockIdx.y * 128;
    const int n0 = blockIdx.x * 128;
    const int z  = blockIdx.z;

    const __half* A = Abase + (size_t)z * Mrows * (size_t)ldA;
    const float* bias = (z == 0) ? b0p : (z == 1) ? b1p : b2p;
    float* out = outBase + (size_t)z * Mrows * Cc;

    float acc[4][4][4];
    #pragma unroll
    for (int i = 0; i < 4; i++)
        #pragma unroll
        for (int j = 0; j < 4; j++)
            #pragma unroll
            for (int r = 0; r < 4; r++) acc[i][j][r] = 0.f;

    const int lr = tid >> 3;
    const int lc = tid & 7;

    const int arow = wm * 64 + (lane & 15);
    const uint32_t amask = (uint32_t)((arow & 7) << 4);
    const uint32_t akb0 = (uint32_t)((lane >> 4) * 16);
    const int brow = wn * 32 + (lane & 7) + ((lane >> 4) & 1) * 8;
    const uint32_t bmask = (uint32_t)((brow & 7) << 4);
    const uint32_t bkb0 = (uint32_t)(((lane >> 3) & 1) * 16);

    auto doLoad = [&](int it, int stage) {
        int in = (it & 7) * 64;
        int seg = it >> 3;
        int aoff, woff;
        if (isBranch) {
            aoff = (seg == 2 ? 512 : 0) + in;
            woff = (seg == 1 ? 512 : 0) + in;
        } else {
            aoff = in;
            woff = seg * 512 + in;
        }
        const __half* Ag = A + (size_t)m0 * ldA + aoff;
        const __half* Wg = W + (size_t)n0 * 1024 + woff;
        uint32_t as = sbase + stage * 32768;
        uint32_t bs = as + 16384;
        #pragma unroll
        for (int u = 0; u < 4; u++) {
            int r = lr + u * 32;
            uint32_t d = (uint32_t)SW128(r * 128 + lc * 16);
            cpa16(as + d, Ag + (size_t)r * ldA + lc * 8);
            cpa16(bs + d, Wg + (size_t)r * 1024 + lc * 8);
        }
    };

    doLoad(0, 0); CPA_COMMIT();
    doLoad(1, 1); CPA_COMMIT();

    for (int it = 0; it < kIters; it++) {
        if (it + 1 < kIters) { CPA_WAIT(1); } else { CPA_WAIT(0); }
        __syncthreads();
        if (it + 2 < kIters) {
            doLoad(it + 2, (it + 2) % 3);
            CPA_COMMIT();
        }
        const uint32_t as = sbase + (it % 3) * 32768;
        const uint32_t bs = as + 16384;
        #pragma unroll
        for (int ks = 0; ks < 4; ks++) {
            uint32_t ar[4][4];
            #pragma unroll
            for (int mi = 0; mi < 4; mi++) {
                uint32_t addr = as + (uint32_t)(arow + mi * 16) * 128
                              + (((uint32_t)(ks * 32) + akb0) ^ amask);
                ldsm4(ar[mi][0], ar[mi][1], ar[mi][2], ar[mi][3], addr);
            }
            uint32_t br[2][4];
            #pragma unroll
            for (int nh = 0; nh < 2; nh++) {
                uint32_t addr = bs + (uint32_t)(brow + nh * 16) * 128
                              + (((uint32_t)(ks * 32) + bkb0) ^ bmask);
                ldsm4(br[nh][0], br[nh][1], br[nh][2], br[nh][3], addr);
            }
            #pragma unroll
            for (int mi = 0; mi < 4; mi++)
                #pragma unroll
                for (int ni = 0; ni < 4; ni++) {
                    int nh = ni >> 1, p = ni & 1;
                    mma16816(acc[mi][ni], ar[mi], br[nh][p*2], br[nh][p*2+1]);
                }
        }
    }

    // ---- epilogue: unscale + bias, store, fused column stats ----
    __syncthreads();                      // smem now reused for stats
    float* spart = (float*)smem;          // [2 (s/s2)][2 (wm)][128]

    float ls[8], ls2[8];
    #pragma unroll
    for (int j = 0; j < 8; j++) { ls[j] = 0.f; ls2[j] = 0.f; }

    #pragma unroll
    for (int mi = 0; mi < 4; mi++) {
        int r0 = m0 + wm * 64 + mi * 16 + (lane >> 2);
        #pragma unroll
        for (int ni = 0; ni < 4; ni++) {
            int n = n0 + wn * 32 + ni * 8 + (lane & 3) * 2;
            float bb0 = bias[n], bb1 = bias[n + 1];
            float a0 = acc[mi][ni][0] * WUNSCALE + bb0;
            float a1 = acc[mi][ni][1] * WUNSCALE + bb1;
            float a2 = acc[mi][ni][2] * WUNSCALE + bb0;
            float a3 = acc[mi][ni][3] * WUNSCALE + bb1;
            float2 v0 = { a0, a1 };
            float2 v1 = { a2, a3 };
            *(float2*)(out + (size_t)r0 * Cc + n) = v0;
            *(float2*)(out + (size_t)(r0 + 8) * Cc + n) = v1;
            ls [ni*2]   += a0 + a2;
            ls2[ni*2]   += a0*a0 + a2*a2;
            ls [ni*2+1] += a1 + a3;
            ls2[ni*2+1] += a1*a1 + a3*a3;
        }
    }
    #pragma unroll
    for (int o = 4; o < 32; o <<= 1) {
        #pragma unroll
        for (int j = 0; j < 8; j++) {
            ls[j]  += __shfl_xor_sync(0xffffffffu, ls[j],  o);
            ls2[j] += __shfl_xor_sync(0xffffffffu, ls2[j], o);
        }
    }
    if (lane < 4) {
        #pragma unroll
        for (int j = 0; j < 8; j++) {
            int col = wn * 32 + (j >> 1) * 8 + lane * 2 + (j & 1);
            spart[wm * 128 + col]       = ls[j];
            spart[256 + wm * 128 + col] = ls2[j];
        }
    }
    __syncthreads();
    if (tid < 128) {
        float s  = spart[tid] + spart[128 + tid];
        float s2 = spart[256 + tid] + spart[384 + tid];
        int n = n0 + tid;
        g_part[((size_t)(z * 96 + blockIdx.y) * 2 + 0) * Cc + n] = s;
        g_part[((size_t)(z * 96 + blockIdx.y) * 2 + 1) * Cc + n] = s2;
    }
}

// ---------------- BN final stats (parallel: grid (nz,4), block 512) ----------
__global__ void __launch_bounds__(512) bn_stats_final()
{
    __shared__ float sp[8][128];
    int z  = blockIdx.x;
    int cb = blockIdx.y;                   // 0..3 -> channels cb*128..+127
    int cl = threadIdx.x & 127;
    int rg = threadIdx.x >> 7;             // 0..3
    int c  = cb * 128 + cl;
    float s = 0.f, s2 = 0.f;
    for (int i = 0; i < 24; i++) {
        int by = rg * 24 + i;
        s  += g_part[((size_t)(z * 96 + by) * 2 + 0) * Cc + c];
        s2 += g_part[((size_t)(z * 96 + by) * 2 + 1) * Cc + c];
    }
    sp[rg][cl] = s;
    sp[4 + rg][cl] = s2;
    __syncthreads();
    if (threadIdx.x < 128) {
        float ts  = (sp[0][cl] + sp[1][cl]) + (sp[2][cl] + sp[3][cl]);
        float ts2 = (sp[4][cl] + sp[5][cl]) + (sp[6][cl] + sp[7][cl]);
        float mean = ts / (float)Mrows;
        float var  = ts2 / (float)Mrows - mean * mean;
        g_mean[z * Cc + c] = mean;
        g_rstd[z * Cc + c] = rsqrtf(var + EPSb);
    }
}

// ------- merged BN apply + LIF + ballot bit-pack (q/k/v) ---------------------
__global__ void __launch_bounds__(512) bn_lif_bits(
    const float* __restrict__ Ybase,
    const float* __restrict__ g0, const float* __restrict__ g1,
    const float* __restrict__ g2,
    const float* __restrict__ e0, const float* __restrict__ e1,
    const float* __restrict__ e2,
    uint32_t* __restrict__ w0, uint32_t* __restrict__ w1,
    uint32_t* __restrict__ w2)
{
    int z = blockIdx.y;
    const float* Y = Ybase + (size_t)z * Mrows * Cc;
    const float* gamma = (z == 0) ? g0 : (z == 1) ? g1 : g2;
    const float* beta  = (z == 0) ? e0 : (z == 1) ? e1 : e2;
    uint32_t* bits     = (z == 0) ? w0 : (z == 1) ? w1 : w2;

    int bn = blockIdx.x;
    int c  = threadIdx.x;
    float mean = g_mean[z * Cc + c], rstd = g_rstd[z * Cc + c];
    float ga = gamma[c], be = beta[c];
    float mem = 0.f, spike = 0.f;
    #pragma unroll
    for (int t = 0; t < Tt; t++) {
        float y = Y[((size_t)t*4096 + bn)*Cc + c];
        float v = ga * (y - mean) * rstd + be;
        mem = (t == 0) ? v : (mem * DECAY * (1.f - spike) + v);
        bool fire = mem > THRESH;
        spike = fire ? 1.f : 0.f;
        unsigned mask = __ballot_sync(0xffffffffu, fire);
        if ((c & 31) == 0)
            bits[((size_t)t*4096 + bn)*16 + (c >> 5)] = mask;
    }
}

// ------- final stage: BN apply + LIF, write float spikes ---------------------
__global__ void __launch_bounds__(512) bn_lif_out(
    const float* __restrict__ Y, const float* __restrict__ gamma,
    const float* __restrict__ beta, float* __restrict__ out)
{
    int bn = blockIdx.x;
    int c  = threadIdx.x;
    float mean = g_mean[c], rstd = g_rstd[c];
    float ga = gamma[c], be = beta[c];
    float mem = 0.f, spike = 0.f;
    #pragma unroll
    for (int t = 0; t < Tt; t++) {
        float y = Y[((size_t)t*4096 + bn)*Cc + c];
        float v = ga * (y - mean) * rstd + be;
        mem = (t == 0) ? v : (mem * DECAY * (1.f - spike) + v);
        spike = (mem > THRESH) ? 1.f : 0.f;
        out[((size_t)t*4096 + bn)*Cc + c] = spike;
    }
}

// --- LIF on attention output -> fp16 spikes ----------------------------------
__global__ void __launch_bounds__(256) lif_to_half(
    const float* __restrict__ X, __half* __restrict__ A)
{
    uint32_t gid = blockIdx.x * 256 + threadIdx.x;
    int bn = gid >> 8;
    int c2 = (gid & 255) << 1;
    float mem0 = 0.f, mem1 = 0.f, sp0 = 0.f, sp1 = 0.f;
    #pragma unroll
    for (int t = 0; t < Tt; t++) {
        float2 v = *(const float2*)(X + (size_t)t*BNC + (size_t)bn*Cc + c2);
        mem0 = (t == 0) ? v.x : (mem0 * DECAY * (1.f - sp0) + v.x);
        mem1 = (t == 0) ? v.y : (mem1 * DECAY * (1.f - sp1) + v.y);
        sp0 = (mem0 > THRESH) ? 1.f : 0.f;
        sp1 = (mem1 > THRESH) ? 1.f : 0.f;
        *(__half2*)(A + ((size_t)t*4096 + bn) * Cc + c2) =
            __halves2half2(__float2half(sp0), __float2half(sp1));
    }
}

// ---------------- G[j,d] = sum_m k[m,j]*v[m,d]  (per t,b,h) ------------------
__global__ void __launch_bounds__(256) build_G()
{
    int tbh = blockIdx.x;
    int h = tbh & 7;
    int tb = tbh >> 3;
    int tid = threadIdx.x;
    int lane = tid & 31;

    __shared__ uint32_t kc[64][32];
    __shared__ uint32_t vc[64][32];

    for (int m0 = tid; m0 < Nn; m0 += 256) {
        size_t row = (size_t)tb * Nn + m0;
        uint32_t k0 = g_kw[row*16 + 2*h],  k1 = g_kw[row*16 + 2*h + 1];
        uint32_t v0 = g_vw[row*16 + 2*h],  v1 = g_vw[row*16 + 2*h + 1];
        int w = m0 >> 5;
        #pragma unroll
        for (int j = 0; j < 32; j++) {
            unsigned mk = __ballot_sync(0xffffffffu, (k0 >> j) & 1u);
            if (lane == 0) kc[j][w] = mk;
            unsigned mk2 = __ballot_sync(0xffffffffu, (k1 >> j) & 1u);
            if (lane == 0) kc[j + 32][w] = mk2;
            unsigned mv = __ballot_sync(0xffffffffu, (v0 >> j) & 1u);
            if (lane == 0) vc[j][w] = mv;
            unsigned mv2 = __ballot_sync(0xffffffffu, (v1 >> j) & 1u);
            if (lane == 0) vc[j + 32][w] = mv2;
        }
    }
    __syncthreads();

    for (int e = tid; e < 4096; e += 256) {
        int j = e >> 6, d = e & 63;
        int s = 0;
        #pragma unroll
        for (int w = 0; w < 32; w++)
            s += __popc(kc[j][w] & vc[d][w]);
        g_G[(size_t)tbh*4096 + e] = (float)s;
    }
}

// ------- X[n, h*64+d] = SCALE * sum_j q[n,j] * G[j,d]  (per t,b,h) -----------
__global__ void __launch_bounds__(256) attn_x(float* __restrict__ Xout)
{
    int tbh = blockIdx.y;
    int h = tbh & 7;
    int tb = tbh >> 3;
    int d   = threadIdx.x & 63;
    int grp = threadIdx.x >> 6;

    float Greg[64];
    #pragma unroll
    for (int j = 0; j < 64; j++)
        Greg[j] = g_G[(size_t)tbh*4096 + j*64 + d];

    for (int ns = 0; ns < 16; ns++) {
        int n = blockIdx.x*64 + grp*16 + ns;
        size_t row = (size_t)tb * Nn + n;
        uint32_t q0 = g_qw[row*16 + 2*h];
        uint32_t q1 = g_qw[row*16 + 2*h + 1];
        unsigned long long qb = (unsigned long long)q0 |
                                ((unsigned long long)q1 << 32);
        float acc = 0.f;
        #pragma unroll
        for (int j = 0; j < 64; j++)
            if ((qb >> j) & 1ULL) acc += Greg[j];
        Xout[row*Cc + h*64 + d] = SCALE * acc;
    }
}

// ---------------- host launcher ----------------------------------------------
extern "C" void kernel_launch(void* const* d_in, const int* in_sizes, int n_in,
                              void* d_out, int out_size)
{
    (void)in_sizes; (void)n_in; (void)out_size;
    const float* q  = (const float*)d_in[0];
    const float* k  = (const float*)d_in[1];
    const float* v  = (const float*)d_in[2];
    const float* Wq = (const float*)d_in[3];
    const float* bq = (const float*)d_in[4];
    const float* gq = (const float*)d_in[5];
    const float* betaq = (const float*)d_in[6];
    const float* Wk = (const float*)d_in[7];
    const float* bk = (const float*)d_in[8];
    const float* gk = (const float*)d_in[9];
    const float* betak = (const float*)d_in[10];
    const float* Wv = (const float*)d_in[11];
    const float* bv = (const float*)d_in[12];
    const float* gv = (const float*)d_in[13];
    const float* betav = (const float*)d_in[14];
    const float* Wp = (const float*)d_in[15];
    const float* bp = (const float*)d_in[16];
    const float* gp = (const float*)d_in[17];
    const float* betap = (const float*)d_in[18];
    float* out = (float*)d_out;

    float *S0;
    __half *Ac, *Wc;
    uint32_t *qw, *kw, *vw;
    cudaGetSymbolAddress((void**)&S0, g_S0);
    cudaGetSymbolAddress((void**)&Ac, g_Ac);
    cudaGetSymbolAddress((void**)&Wc, g_Wc);
    cudaGetSymbolAddress((void**)&qw, g_qw);
    cudaGetSymbolAddress((void**)&kw, g_kw);
    cudaGetSymbolAddress((void**)&vw, g_vw);

    cudaFuncSetAttribute(gemm_mma,
                         cudaFuncAttributeMaxDynamicSharedMemorySize, GEMM_SMEM);

    // splits
    split_W4<<<dim3(256, 4), 256>>>(Wq, Wk, Wv, Wp, Wc);
    split_A3<<<dim3(6144, 3), 256>>>(q, k, v, Ac);

    // --- all 3 branch GEMMs in one launch (fused BN partial stats) ---
    gemm_mma<<<dim3(4, 96, 3), 256, GEMM_SMEM>>>(
        Ac, Wc, bq, bk, bv, S0, 24, 1024, 1);
    bn_stats_final<<<dim3(3, 4), 512>>>();
    bn_lif_bits<<<dim3(4096, 3), 512>>>(S0, gq, gk, gv, betaq, betak, betav,
                                        qw, kw, vw);

    // --- attention (collapsed: X = Q (K^T V) * SCALE), exact integer math ---
    build_G<<<Tt*Bb*Hh, 256>>>();
    attn_x<<<dim3(16, 96), 256>>>(S0);

    // --- LIF on attention output -> fp16 spike A ---
    lif_to_half<<<4096, 256>>>(S0, Ac);

    // --- projection + BN + LIF -> output ---
    gemm_mma<<<dim3(4, 96, 1), 256, GEMM_SMEM>>>(
        Ac, Wc + (size_t)3 * Cc * 1024, bp, bp, bp, S0, 16, 512, 0);
    bn_stats_final<<<dim3(1, 4), 512>>>();
    bn_lif_out<<<4096, 512>>>(S0, gp, betap, out);
}

// round 11
// speedup vs baseline: 1.0499x; 1.0059x over previous
#include <cuda_runtime.h>
#include <cuda_fp16.h>
#include <cstdint>

// Problem constants
#define Tt 3
#define Bb 4
#define Nn 1024
#define Cc 512
#define Hh 8
#define Mrows (Tt*Bb*Nn)        // 12288
#define BNC (Bb*Nn*Cc)          // 2097152
#define THRESH 0.5f
#define DECAY 0.25f
#define SCALE 0.125f
#define EPSb 1e-5f
#define WSCALE 1024.0f
#define WUNSCALE (1.0f/1024.0f)

#define GEMM_SMEM (2*32768)     // 2 stages x (16KB A + 16KB B)

// ---------------- scratch (static device globals; no allocation) -------------
__device__ float  g_S0[3 * Mrows * Cc];           // 75.5 MB fp32 GEMM outputs
__device__ __half g_Ac[3 * Mrows * 1024];         // 75.5 MB split-A / spike-A
__device__ __half g_Wc[4 * Cc * 1024];            // 4 MB split weights (x1024)
__device__ uint32_t g_qw[Tt*Bb*Nn*16];
__device__ uint32_t g_kw[Tt*Bb*Nn*16];
__device__ uint32_t g_vw[Tt*Bb*Nn*16];
__device__ float    g_G[Tt*Bb*Hh*64*64];
__device__ float    g_part[3*96*2*Cc];            // per-(z, m-tile) BN partials
__device__ float    g_mean[3*Cc];
__device__ float    g_rstd[3*Cc];

// ---------------- helpers ----------------------------------------------------
__device__ __forceinline__ uint32_t smem_u32(const void* p) {
    uint32_t a;
    asm("{ .reg .u64 t; cvta.to.shared.u64 t, %1; cvt.u32.u64 %0, t; }"
        : "=r"(a) : "l"(p));
    return a;
}
#define SW128(off) ((off) ^ (((off) >> 3) & 0x70))

__device__ __forceinline__ void cpa16(uint32_t s, const void* g) {
    asm volatile("cp.async.cg.shared.global [%0], [%1], 16;"
                 :: "r"(s), "l"(g));
}
#define CPA_COMMIT()  asm volatile("cp.async.commit_group;" ::: "memory")
#define CPA_WAIT(n)   asm volatile("cp.async.wait_group %0;" :: "n"(n) : "memory")

__device__ __forceinline__ void ldsm4(uint32_t& r0, uint32_t& r1,
                                      uint32_t& r2, uint32_t& r3, uint32_t a) {
    asm volatile("ldmatrix.sync.aligned.m8n8.x4.shared.b16 {%0,%1,%2,%3}, [%4];"
                 : "=r"(r0), "=r"(r1), "=r"(r2), "=r"(r3) : "r"(a));
}
__device__ __forceinline__ void mma16816(float* c, const uint32_t* a,
                                         uint32_t b0, uint32_t b1) {
    asm volatile(
        "mma.sync.aligned.m16n8k16.row.col.f32.f16.f16.f32 "
        "{%0,%1,%2,%3}, {%4,%5,%6,%7}, {%8,%9}, {%0,%1,%2,%3};"
        : "+f"(c[0]), "+f"(c[1]), "+f"(c[2]), "+f"(c[3])
        : "r"(a[0]), "r"(a[1]), "r"(a[2]), "r"(a[3]), "r"(b0), "r"(b1));
}

// ---------------- fp32 -> 2x fp16 split --------------------------------------
__device__ __forceinline__ void split2(float x, __half& h, __half& m) {
    h = __float2half(x);
    m = __float2half(x - __half2float(h));
}

// ---- merged A split: q,k,v -> g_Ac[z], layout [hi(512) | mid(512)] ----------
__global__ void __launch_bounds__(256) split_A3(
    const float* __restrict__ q, const float* __restrict__ k,
    const float* __restrict__ v, __half* __restrict__ out)
{
    int z = blockIdx.y;
    const float* in = (z == 0) ? q : (z == 1) ? k : v;
    uint32_t gid = blockIdx.x * 256 + threadIdx.x;  // over Mrows*128 quads
    size_t m = gid >> 7;
    int c4 = (gid & 127) << 2;
    float4 x = *(const float4*)(in + m * Cc + c4);
    __half h0,m0,h1,m1,h2,m2,h3,m3;
    split2(x.x, h0, m0); split2(x.y, h1, m1);
    split2(x.z, h2, m2); split2(x.w, h3, m3);
    __half2* o = (__half2*)(out + (size_t)z * Mrows * 1024 + m * 1024 + c4);
    o[0] = __halves2half2(h0, h1);
    o[1] = __halves2half2(h2, h3);
    o[256] = __halves2half2(m0, m1);     // +512 halves
    o[257] = __halves2half2(m2, m3);
}

// ---- merged W split: Wq,Wk,Wv,Wp -> g_Wc[y], scaled x1024 -------------------
__global__ void __launch_bounds__(256) split_W4(
    const float* __restrict__ w0, const float* __restrict__ w1,
    const float* __restrict__ w2, const float* __restrict__ w3,
    __half* __restrict__ out)
{
    int y = blockIdx.y;
    const float* W = (y == 0) ? w0 : (y == 1) ? w1 : (y == 2) ? w2 : w3;
    uint32_t gid = blockIdx.x * 256 + threadIdx.x;  // over 512*128 quads
    size_t n = gid >> 7;
    int c4 = (gid & 127) << 2;
    float4 x = *(const float4*)(W + n * Cc + c4);
    x.x *= WSCALE; x.y *= WSCALE; x.z *= WSCALE; x.w *= WSCALE;
    __half h0,m0,h1,m1,h2,m2,h3,m3;
    split2(x.x, h0, m0); split2(x.y, h1, m1);
    split2(x.z, h2, m2); split2(x.w, h3, m3);
    __half2* o = (__half2*)(out + (size_t)y * Cc * 1024 + n * 1024 + c4);
    o[0] = __halves2half2(h0, h1);
    o[1] = __halves2half2(h2, h3);
    o[256] = __halves2half2(m0, m1);
    o[257] = __halves2half2(m2, m3);
}

// ---------------- fp16 mma.sync GEMM + fused BN partial stats ----------------
// out[m,n] = (sum_k' A*W)*2^-10 + bias[n]. 3-product split via segment mapping.
// isBranch=1: A=[Ah|Am] ldA=1024, 24 iters, segs (Ah,Wh),(Ah,Wm),(Am,Wh)
// isBranch=0: A=spikes ldA=512, 16 iters, segs (A,Wh),(A,Wm)
// 2-stage pipeline + 2 CTAs/SM for sync-bubble overlap.
__global__ void __launch_bounds__(256, 2) gemm_mma(
    const __half* __restrict__ Abase, const __half* __restrict__ W,
    const float* __restrict__ b0p, const float* __restrict__ b1p,
    const float* __restrict__ b2p, float* __restrict__ outBase,
    int kIters, int ldA, int isBranch)
{
    extern __shared__ char smem[];
    const uint32_t sbase = smem_u32(smem);
    const int tid = threadIdx.x;
    const int lane = tid & 31;
    const int wid = tid >> 5;
    const int wm = wid & 1;
    const int wn = wid >> 1;
    const int m0 = blockIdx.y * 128;
    const int n0 = blockIdx.x * 128;
    const int z  = blockIdx.z;

    const __half* A = Abase + (size_t)z * Mrows * (size_t)ldA;
    const float* bias = (z == 0) ? b0p : (z == 1) ? b1p : b2p;
    float* out = outBase + (size_t)z * Mrows * Cc;

    float acc[4][4][4];
    #pragma unroll
    for (int i = 0; i < 4; i++)
        #pragma unroll
        for (int j = 0; j < 4; j++)
            #pragma unroll
            for (int r = 0; r < 4; r++) acc[i][j][r] = 0.f;

    const int lr = tid >> 3;
    const int lc = tid & 7;

    const int arow = wm * 64 + (lane & 15);
    const uint32_t amask = (uint32_t)((arow & 7) << 4);
    const uint32_t akb0 = (uint32_t)((lane >> 4) * 16);
    const int brow = wn * 32 + (lane & 7) + ((lane >> 4) & 1) * 8;
    const uint32_t bmask = (uint32_t)((brow & 7) << 4);
    const uint32_t bkb0 = (uint32_t)(((lane >> 3) & 1) * 16);

    auto doLoad = [&](int it, int stage) {
        int in = (it & 7) * 64;
        int seg = it >> 3;
        int aoff, woff;
        if (isBranch) {
            aoff = (seg == 2 ? 512 : 0) + in;
            woff = (seg == 1 ? 512 : 0) + in;
        } else {
            aoff = in;
            woff = seg * 512 + in;
        }
        const __half* Ag = A + (size_t)m0 * ldA + aoff;
        const __half* Wg = W + (size_t)n0 * 1024 + woff;
        uint32_t as = sbase + stage * 32768;
        uint32_t bs = as + 16384;
        #pragma unroll
        for (int u = 0; u < 4; u++) {
            int r = lr + u * 32;
            uint32_t d = (uint32_t)SW128(r * 128 + lc * 16);
            cpa16(as + d, Ag + (size_t)r * ldA + lc * 8);
            cpa16(bs + d, Wg + (size_t)r * 1024 + lc * 8);
        }
    };

    doLoad(0, 0);
    CPA_COMMIT();

    for (int it = 0; it < kIters; it++) {
        const int st = it & 1;
        if (it + 1 < kIters) {
            doLoad(it + 1, st ^ 1);
            CPA_COMMIT();
            CPA_WAIT(1);
        } else {
            CPA_WAIT(0);
        }
        __syncthreads();

        const uint32_t as = sbase + st * 32768;
        const uint32_t bs = as + 16384;
        #pragma unroll
        for (int ks = 0; ks < 4; ks++) {
            uint32_t ar[4][4];
            #pragma unroll
            for (int mi = 0; mi < 4; mi++) {
                uint32_t addr = as + (uint32_t)(arow + mi * 16) * 128
                              + (((uint32_t)(ks * 32) + akb0) ^ amask);
                ldsm4(ar[mi][0], ar[mi][1], ar[mi][2], ar[mi][3], addr);
            }
            uint32_t br[2][4];
            #pragma unroll
            for (int nh = 0; nh < 2; nh++) {
                uint32_t addr = bs + (uint32_t)(brow + nh * 16) * 128
                              + (((uint32_t)(ks * 32) + bkb0) ^ bmask);
                ldsm4(br[nh][0], br[nh][1], br[nh][2], br[nh][3], addr);
            }
            #pragma unroll
            for (int mi = 0; mi < 4; mi++)
                #pragma unroll
                for (int ni = 0; ni < 4; ni++) {
                    int nh = ni >> 1, p = ni & 1;
                    mma16816(acc[mi][ni], ar[mi], br[nh][p*2], br[nh][p*2+1]);
                }
        }
        __syncthreads();
    }

    // ---- epilogue: unscale + bias, store, fused column stats ----
    float* spart = (float*)smem;          // [2 (s/s2)][2 (wm)][128]

    float ls[8], ls2[8];
    #pragma unroll
    for (int j = 0; j < 8; j++) { ls[j] = 0.f; ls2[j] = 0.f; }

    #pragma unroll
    for (int mi = 0; mi < 4; mi++) {
        int r0 = m0 + wm * 64 + mi * 16 + (lane >> 2);
        #pragma unroll
        for (int ni = 0; ni < 4; ni++) {
            int n = n0 + wn * 32 + ni * 8 + (lane & 3) * 2;
            float bb0 = bias[n], bb1 = bias[n + 1];
            float a0 = acc[mi][ni][0] * WUNSCALE + bb0;
            float a1 = acc[mi][ni][1] * WUNSCALE + bb1;
            float a2 = acc[mi][ni][2] * WUNSCALE + bb0;
            float a3 = acc[mi][ni][3] * WUNSCALE + bb1;
            float2 v0 = { a0, a1 };
            float2 v1 = { a2, a3 };
            *(float2*)(out + (size_t)r0 * Cc + n) = v0;
            *(float2*)(out + (size_t)(r0 + 8) * Cc + n) = v1;
            ls [ni*2]   += a0 + a2;
            ls2[ni*2]   += a0*a0 + a2*a2;
            ls [ni*2+1] += a1 + a3;
            ls2[ni*2+1] += a1*a1 + a3*a3;
        }
    }
    #pragma unroll
    for (int o = 4; o < 32; o <<= 1) {
        #pragma unroll
        for (int j = 0; j < 8; j++) {
            ls[j]  += __shfl_xor_sync(0xffffffffu, ls[j],  o);
            ls2[j] += __shfl_xor_sync(0xffffffffu, ls2[j], o);
        }
    }
    if (lane < 4) {
        #pragma unroll
        for (int j = 0; j < 8; j++) {
            int col = wn * 32 + (j >> 1) * 8 + lane * 2 + (j & 1);
            spart[wm * 128 + col]       = ls[j];
            spart[256 + wm * 128 + col] = ls2[j];
        }
    }
    __syncthreads();
    if (tid < 128) {
        float s  = spart[tid] + spart[128 + tid];
        float s2 = spart[256 + tid] + spart[384 + tid];
        int n = n0 + tid;
        g_part[((size_t)(z * 96 + blockIdx.y) * 2 + 0) * Cc + n] = s;
        g_part[((size_t)(z * 96 + blockIdx.y) * 2 + 1) * Cc + n] = s2;
    }
}

// ---------------- BN final stats (parallel: grid (nz,4), block 512) ----------
__global__ void __launch_bounds__(512) bn_stats_final()
{
    __shared__ float sp[8][128];
    int z  = blockIdx.x;
    int cb = blockIdx.y;                   // 0..3 -> channels cb*128..+127
    int cl = threadIdx.x & 127;
    int rg = threadIdx.x >> 7;             // 0..3
    int c  = cb * 128 + cl;
    float s = 0.f, s2 = 0.f;
    for (int i = 0; i < 24; i++) {
        int by = rg * 24 + i;
        s  += g_part[((size_t)(z * 96 + by) * 2 + 0) * Cc + c];
        s2 += g_part[((size_t)(z * 96 + by) * 2 + 1) * Cc + c];
    }
    sp[rg][cl] = s;
    sp[4 + rg][cl] = s2;
    __syncthreads();
    if (threadIdx.x < 128) {
        float ts  = (sp[0][cl] + sp[1][cl]) + (sp[2][cl] + sp[3][cl]);
        float ts2 = (sp[4][cl] + sp[5][cl]) + (sp[6][cl] + sp[7][cl]);
        float mean = ts / (float)Mrows;
        float var  = ts2 / (float)Mrows - mean * mean;
        g_mean[z * Cc + c] = mean;
        g_rstd[z * Cc + c] = rsqrtf(var + EPSb);
    }
}

// ------- merged BN apply + LIF + ballot bit-pack (q/k/v) ---------------------
__global__ void __launch_bounds__(512) bn_lif_bits(
    const float* __restrict__ Ybase,
    const float* __restrict__ g0, const float* __restrict__ g1,
    const float* __restrict__ g2,
    const float* __restrict__ e0, const float* __restrict__ e1,
    const float* __restrict__ e2,
    uint32_t* __restrict__ w0, uint32_t* __restrict__ w1,
    uint32_t* __restrict__ w2)
{
    int z = blockIdx.y;
    const float* Y = Ybase + (size_t)z * Mrows * Cc;
    const float* gamma = (z == 0) ? g0 : (z == 1) ? g1 : g2;
    const float* beta  = (z == 0) ? e0 : (z == 1) ? e1 : e2;
    uint32_t* bits     = (z == 0) ? w0 : (z == 1) ? w1 : w2;

    int bn = blockIdx.x;
    int c  = threadIdx.x;
    float mean = g_mean[z * Cc + c], rstd = g_rstd[z * Cc + c];
    float ga = gamma[c], be = beta[c];
    float mem = 0.f, spike = 0.f;
    #pragma unroll
    for (int t = 0; t < Tt; t++) {
        float y = Y[((size_t)t*4096 + bn)*Cc + c];
        float v = ga * (y - mean) * rstd + be;
        mem = (t == 0) ? v : (mem * DECAY * (1.f - spike) + v);
        bool fire = mem > THRESH;
        spike = fire ? 1.f : 0.f;
        unsigned mask = __ballot_sync(0xffffffffu, fire);
        if ((c & 31) == 0)
            bits[((size_t)t*4096 + bn)*16 + (c >> 5)] = mask;
    }
}

// ------- final stage: BN apply + LIF, write float spikes ---------------------
__global__ void __launch_bounds__(512) bn_lif_out(
    const float* __restrict__ Y, const float* __restrict__ gamma,
    const float* __restrict__ beta, float* __restrict__ out)
{
    int bn = blockIdx.x;
    int c  = threadIdx.x;
    float mean = g_mean[c], rstd = g_rstd[c];
    float ga = gamma[c], be = beta[c];
    float mem = 0.f, spike = 0.f;
    #pragma unroll
    for (int t = 0; t < Tt; t++) {
        float y = Y[((size_t)t*4096 + bn)*Cc + c];
        float v = ga * (y - mean) * rstd + be;
        mem = (t == 0) ? v : (mem * DECAY * (1.f - spike) + v);
        spike = (mem > THRESH) ? 1.f : 0.f;
        out[((size_t)t*4096 + bn)*Cc + c] = spike;
    }
}

// --- LIF on attention output -> fp16 spikes ----------------------------------
__global__ void __launch_bounds__(256) lif_to_half(
    const float* __restrict__ X, __half* __restrict__ A)
{
    uint32_t gid = blockIdx.x * 256 + threadIdx.x;
    int bn = gid >> 8;
    int c2 = (gid & 255) << 1;
    float mem0 = 0.f, mem1 = 0.f, sp0 = 0.f, sp1 = 0.f;
    #pragma unroll
    for (int t = 0; t < Tt; t++) {
        float2 v = *(const float2*)(X + (size_t)t*BNC + (size_t)bn*Cc + c2);
        mem0 = (t == 0) ? v.x : (mem0 * DECAY * (1.f - sp0) + v.x);
        mem1 = (t == 0) ? v.y : (mem1 * DECAY * (1.f - sp1) + v.y);
        sp0 = (mem0 > THRESH) ? 1.f : 0.f;
        sp1 = (mem1 > THRESH) ? 1.f : 0.f;
        *(__half2*)(A + ((size_t)t*4096 + bn) * Cc + c2) =
            __halves2half2(__float2half(sp0), __float2half(sp1));
    }
}

// ---------------- G[j,d] = sum_m k[m,j]*v[m,d]  (per t,b,h) ------------------
__global__ void __launch_bounds__(256) build_G()
{
    int tbh = blockIdx.x;
    int h = tbh & 7;
    int tb = tbh >> 3;
    int tid = threadIdx.x;
    int lane = tid & 31;

    __shared__ uint32_t kc[64][32];
    __shared__ uint32_t vc[64][32];

    for (int m0 = tid; m0 < Nn; m0 += 256) {
        size_t row = (size_t)tb * Nn + m0;
        uint32_t k0 = g_kw[row*16 + 2*h],  k1 = g_kw[row*16 + 2*h + 1];
        uint32_t v0 = g_vw[row*16 + 2*h],  v1 = g_vw[row*16 + 2*h + 1];
        int w = m0 >> 5;
        #pragma unroll
        for (int j = 0; j < 32; j++) {
            unsigned mk = __ballot_sync(0xffffffffu, (k0 >> j) & 1u);
            if (lane == 0) kc[j][w] = mk;
            unsigned mk2 = __ballot_sync(0xffffffffu, (k1 >> j) & 1u);
            if (lane == 0) kc[j + 32][w] = mk2;
            unsigned mv = __ballot_sync(0xffffffffu, (v0 >> j) & 1u);
            if (lane == 0) vc[j][w] = mv;
            unsigned mv2 = __ballot_sync(0xffffffffu, (v1 >> j) & 1u);
            if (lane == 0) vc[j + 32][w] = mv2;
        }
    }
    __syncthreads();

    for (int e = tid; e < 4096; e += 256) {
        int j = e >> 6, d = e & 63;
        int s = 0;
        #pragma unroll
        for (int w = 0; w < 32; w++)
            s += __popc(kc[j][w] & vc[d][w]);
        g_G[(size_t)tbh*4096 + e] = (float)s;
    }
}

// ------- X[n, h*64+d] = SCALE * sum_j q[n,j] * G[j,d]  (per t,b,h) -----------
__global__ void __launch_bounds__(256) attn_x(float* __restrict__ Xout)
{
    int tbh = blockIdx.y;
    int h = tbh & 7;
    int tb = tbh >> 3;
    int d   = threadIdx.x & 63;
    int grp = threadIdx.x >> 6;

    float Greg[64];
    #pragma unroll
    for (int j = 0; j < 64; j++)
        Greg[j] = g_G[(size_t)tbh*4096 + j*64 + d];

    for (int ns = 0; ns < 16; ns++) {
        int n = blockIdx.x*64 + grp*16 + ns;
        size_t row = (size_t)tb * Nn + n;
        uint32_t q0 = g_qw[row*16 + 2*h];
        uint32_t q1 = g_qw[row*16 + 2*h + 1];
        unsigned long long qb = (unsigned long long)q0 |
                                ((unsigned long long)q1 << 32);
        float acc = 0.f;
        #pragma unroll
        for (int j = 0; j < 64; j++)
            if ((qb >> j) & 1ULL) acc += Greg[j];
        Xout[row*Cc + h*64 + d] = SCALE * acc;
    }
}

// ---------------- host launcher ----------------------------------------------
extern "C" void kernel_launch(void* const* d_in, const int* in_sizes, int n_in,
                              void* d_out, int out_size)
{
    (void)in_sizes; (void)n_in; (void)out_size;
    const float* q  = (const float*)d_in[0];
    const float* k  = (const float*)d_in[1];
    const float* v  = (const float*)d_in[2];
    const float* Wq = (const float*)d_in[3];
    const float* bq = (const float*)d_in[4];
    const float* gq = (const float*)d_in[5];
    const float* betaq = (const float*)d_in[6];
    const float* Wk = (const float*)d_in[7];
    const float* bk = (const float*)d_in[8];
    const float* gk = (const float*)d_in[9];
    const float* betak = (const float*)d_in[10];
    const float* Wv = (const float*)d_in[11];
    const float* bv = (const float*)d_in[12];
    const float* gv = (const float*)d_in[13];
    const float* betav = (const float*)d_in[14];
    const float* Wp = (const float*)d_in[15];
    const float* bp = (const float*)d_in[16];
    const float* gp = (const float*)d_in[17];
    const float* betap = (const float*)d_in[18];
    float* out = (float*)d_out;

    float *S0;
    __half *Ac, *Wc;
    uint32_t *qw, *kw, *vw;
    cudaGetSymbolAddress((void**)&S0, g_S0);
    cudaGetSymbolAddress((void**)&Ac, g_Ac);
    cudaGetSymbolAddress((void**)&Wc, g_Wc);
    cudaGetSymbolAddress((void**)&qw, g_qw);
    cudaGetSymbolAddress((void**)&kw, g_kw);
    cudaGetSymbolAddress((void**)&vw, g_vw);

    cudaFuncSetAttribute(gemm_mma,
                         cudaFuncAttributeMaxDynamicSharedMemorySize, GEMM_SMEM);

    // splits
    split_W4<<<dim3(256, 4), 256>>>(Wq, Wk, Wv, Wp, Wc);
    split_A3<<<dim3(6144, 3), 256>>>(q, k, v, Ac);

    // --- all 3 branch GEMMs in one launch (fused BN partial stats) ---
    gemm_mma<<<dim3(4, 96, 3), 256, GEMM_SMEM>>>(
        Ac, Wc, bq, bk, bv, S0, 24, 1024, 1);
    bn_stats_final<<<dim3(3, 4), 512>>>();
    bn_lif_bits<<<dim3(4096, 3), 512>>>(S0, gq, gk, gv, betaq, betak, betav,
                                        qw, kw, vw);

    // --- attention (collapsed: X = Q (K^T V) * SCALE), exact integer math ---
    build_G<<<Tt*Bb*Hh, 256>>>();
    attn_x<<<dim3(16, 96), 256>>>(S0);

    // --- LIF on attention output -> fp16 spike A ---
    lif_to_half<<<4096, 256>>>(S0, Ac);

    // --- projection + BN + LIF -> output ---
    gemm_mma<<<dim3(4, 96, 1), 256, GEMM_SMEM>>>(
        Ac, Wc + (size_t)3 * Cc * 1024, bp, bp, bp, S0, 16, 512, 0);
    bn_stats_final<<<dim3(1, 4), 512>>>();
    bn_lif_out<<<4096, 512>>>(S0, gp, betap, out);
}